// round 3
// baseline (speedup 1.0000x reference)
#include <cuda_runtime.h>

#define N_FEAT   64
#define N_GATES  64
#define N_OUT    8
#define BASE_C   66      // N_FEAT + 2 (const0, const1)
#define MAX_CONN 130     // BASE_C + N_GATES
#define BT       128     // threads per block = samples per block

// top-2 logit indices per gate, PRE-SCALED by BT (column stride in smem)
__device__ int2 g_top2[N_GATES];

// ---------------------------------------------------------------------------
// Prolog: argmax-2 over available logits per gate. Softmax is monotone, so
// top-2 of probs == top-2 of masked logits. Product a*b is symmetric, so only
// the index SET matters; strict > scan matches jax.lax.top_k tie-breaks anyway.
// ---------------------------------------------------------------------------
__global__ void setup_topk_kernel(const float* __restrict__ gw) {
    int i = threadIdx.x;
    if (i >= N_GATES) return;
    int lim = BASE_C + i;
    float v1 = -3.0e38f, v2 = -3.0e38f;
    int i1 = 0, i2 = 0;
    for (int j = 0; j < lim; j++) {
        float v = gw[i * MAX_CONN + j];
        if (v > v1) { v2 = v1; i2 = i1; v1 = v; i1 = j; }
        else if (v > v2) { v2 = v; i2 = j; }
    }
    g_top2[i] = make_int2(i1 * BT, i2 * BT);   // pre-scaled column offsets
}

__device__ __forceinline__ unsigned long long pack2(float g) {
    unsigned long long r;
    unsigned int gu = __float_as_uint(g);
    asm("mov.b64 %0, {%1,%1};" : "=l"(r) : "r"(gu));
    return r;
}
__device__ __forceinline__ void fma2(unsigned long long& d,
                                     unsigned long long a,
                                     unsigned long long b) {
    asm("fma.rn.f32x2 %0, %1, %2, %3;" : "=l"(d) : "l"(a), "l"(b), "l"(d));
}

// ---------------------------------------------------------------------------
// Main kernel: one thread = one sample, per-thread buffer column in shared
// ([col*BT + tid] -> conflict-free). Operand loads are software-pipelined 3
// gates ahead; distance-1/2 dependencies are register-forwarded via compares
// against compile-time constants, so the smem round-trip (STS -> LDS 29cyc)
// is OFF the serial dependency chain.
// ---------------------------------------------------------------------------
__global__ void __launch_bounds__(BT) circuit_kernel(
    const float* __restrict__ X,
    const float* __restrict__ W,       // [N_GATES, N_OUT]
    const float* __restrict__ scale,   // [N_OUT]
    float* __restrict__ out,           // [n, N_OUT]
    int n)
{
    extern __shared__ float smem[];
    float* buf  = smem;                              // MAX_CONN * BT floats
    float* sw   = smem + MAX_CONN * BT;              // 512 floats (W), 16B-aligned
    int2*  sidx = (int2*)(sw + N_GATES * N_OUT);     // 64 int2 (pre-scaled)

    const int tid = threadIdx.x;
    const long long row = (long long)blockIdx.x * BT + tid;

    #pragma unroll
    for (int k = 0; k < (N_GATES * N_OUT) / BT; k++)
        sw[tid + k * BT] = W[tid + k * BT];
    if (tid < N_GATES) sidx[tid] = g_top2[tid];
    __syncthreads();

    if (row < n) {
        float* bufT = buf + tid;                     // my column base

        // stage my X row (coalesced 8KB/warp via float4)
        const float4* xv = (const float4*)(X + row * N_FEAT);
        #pragma unroll
        for (int c = 0; c < N_FEAT / 4; c++) {
            float4 v = xv[c];
            bufT[(4 * c + 0) * BT] = v.x;
            bufT[(4 * c + 1) * BT] = v.y;
            bufT[(4 * c + 2) * BT] = v.z;
            bufT[(4 * c + 3) * BT] = v.w;
        }
        bufT[64 * BT] = 0.0f;
        bufT[65 * BT] = 1.0f;

        unsigned long long acc0 = 0ull, acc1 = 0ull, acc2 = 0ull, acc3 = 0ull;

        // -------- software pipeline --------
        int2  idx[4];
        float pa[4], pb[4];
        #pragma unroll
        for (int j = 0; j < 4; j++) idx[j] = sidx[j];
        #pragma unroll
        for (int j = 0; j < 3; j++) {                // prologue data loads
            pa[j] = bufT[idx[j].x];
            pb[j] = bufT[idx[j].y];
        }
        float gm1 = 0.0f, gm2 = 0.0f;                // g[i-1], g[i-2]

        #pragma unroll
        for (int i = 0; i < N_GATES; i++) {
            float a = pa[i & 3], b = pb[i & 3];
            const int xs = idx[i & 3].x, ys = idx[i & 3].y;
            if (i >= 1) {                            // distance-1 forward
                const int c1 = (BASE_C + i - 1) * BT;
                a = (xs == c1) ? gm1 : a;
                b = (ys == c1) ? gm1 : b;
            }
            if (i >= 2) {                            // distance-2 forward
                const int c2 = (BASE_C + i - 2) * BT;
                a = (xs == c2) ? gm2 : a;
                b = (ys == c2) ? gm2 : b;
            }
            const float g = 1.0f - a * b;
            bufT[(BASE_C + i) * BT] = g;             // visible to loads below
            gm2 = gm1; gm1 = g;

            // acc += g * W[i,:]  as 4x packed f32x2
            const unsigned long long gg = pack2(g);
            const ulonglong2* wr = (const ulonglong2*)(sw + i * N_OUT);
            ulonglong2 w0 = wr[0], w1 = wr[1];       // 2x LDS.128 broadcast
            fma2(acc0, gg, w0.x);
            fma2(acc1, gg, w0.y);
            fma2(acc2, gg, w1.x);
            fma2(acc3, gg, w1.y);

            // prefetch indices for gate i+4 (slot i&3 is free after use above)
            if (i + 4 < N_GATES) idx[i & 3] = sidx[i + 4];
            // issue operand loads for gate i+3 (smem has gates <= i;
            // refs to i+1/i+2 are garbage here, patched at use)
            if (i + 3 < N_GATES) {
                const int2 t = idx[(i + 3) & 3];
                pa[(i + 3) & 3] = bufT[t.x];
                pb[(i + 3) & 3] = bufT[t.y];
            }
        }

        // unpack, scale, store
        float r[N_OUT];
        asm("mov.b64 {%0,%1}, %2;" : "=r"(*(unsigned*)&r[0]), "=r"(*(unsigned*)&r[1]) : "l"(acc0));
        asm("mov.b64 {%0,%1}, %2;" : "=r"(*(unsigned*)&r[2]), "=r"(*(unsigned*)&r[3]) : "l"(acc1));
        asm("mov.b64 {%0,%1}, %2;" : "=r"(*(unsigned*)&r[4]), "=r"(*(unsigned*)&r[5]) : "l"(acc2));
        asm("mov.b64 {%0,%1}, %2;" : "=r"(*(unsigned*)&r[6]), "=r"(*(unsigned*)&r[7]) : "l"(acc3));

        float4 o0, o1;
        o0.x = r[0] * __ldg(&scale[0]);
        o0.y = r[1] * __ldg(&scale[1]);
        o0.z = r[2] * __ldg(&scale[2]);
        o0.w = r[3] * __ldg(&scale[3]);
        o1.x = r[4] * __ldg(&scale[4]);
        o1.y = r[5] * __ldg(&scale[5]);
        o1.z = r[6] * __ldg(&scale[6]);
        o1.w = r[7] * __ldg(&scale[7]);
        float4* ov = (float4*)(out + row * N_OUT);
        ov[0] = o0;
        ov[1] = o1;
    }
}

// ---------------------------------------------------------------------------
extern "C" void kernel_launch(void* const* d_in, const int* in_sizes, int n_in,
                              void* d_out, int out_size) {
    const float* X     = (const float*)d_in[0];
    const float* gw    = (const float*)d_in[1];
    const float* W     = (const float*)d_in[2];
    const float* scale = (const float*)d_in[3];
    float* out = (float*)d_out;

    const int n = in_sizes[0] / N_FEAT;

    setup_topk_kernel<<<1, N_GATES>>>(gw);

    const size_t smem_bytes =
        (size_t)MAX_CONN * BT * sizeof(float) +
        (size_t)N_GATES * N_OUT * sizeof(float) +
        (size_t)N_GATES * sizeof(int2);

    cudaFuncSetAttribute(circuit_kernel,
                         cudaFuncAttributeMaxDynamicSharedMemorySize,
                         (int)smem_bytes);

    const int grid = (n + BT - 1) / BT;
    circuit_kernel<<<grid, BT, smem_bytes>>>(X, W, scale, out, n);
}

// round 5
// speedup vs baseline: 1.0342x; 1.0342x over previous
#include <cuda_runtime.h>

#define N_FEAT   64
#define N_GATES  64
#define N_OUT    8
#define BASE_C   66                  // N_FEAT + 2
#define MAX_CONN 130
#define BT       64                  // threads per block
#define SPB      (2 * BT)            // samples per block (2 per thread)
#define COLB     (BT * 8)            // byte stride between buffer columns (float2)

// setup results (device), copied into __constant__ before the main kernel
__device__ int2               d_idx[N_GATES];
__device__ unsigned long long d_wdup[N_GATES * N_OUT];

__constant__ int2               c_idx[N_GATES];            // byte offsets, pre-scaled
__constant__ unsigned long long c_w[N_GATES * N_OUT];      // {w*scale, w*scale}

// ---------------------------------------------------------------------------
// Setup: top-2 of masked logits per gate (softmax is monotone -> top-2 of
// logits; strict > scan matches jax.lax.top_k tie-breaking), indices stored
// as BYTE offsets into the packed smem buffer. Also W*scale, duplicated into
// both f32x2 lanes.
// ---------------------------------------------------------------------------
__global__ void setup_kernel(const float* __restrict__ gw,
                             const float* __restrict__ W,
                             const float* __restrict__ scale) {
    int t = threadIdx.x;
    if (t < N_GATES) {
        int lim = BASE_C + t;
        float v1 = -3.0e38f, v2 = -3.0e38f;
        int i1 = 0, i2 = 0;
        for (int j = 0; j < lim; j++) {
            float v = gw[t * MAX_CONN + j];
            if (v > v1) { v2 = v1; i2 = i1; v1 = v; i1 = j; }
            else if (v > v2) { v2 = v; i2 = j; }
        }
        d_idx[t] = make_int2(i1 * COLB, i2 * COLB);
    }
    if (t < N_GATES * N_OUT) {
        int o = t & 7;
        float v = W[t] * scale[o];
        unsigned int u = __float_as_uint(v);
        d_wdup[t] = ((unsigned long long)u << 32) | (unsigned long long)u;
    }
}

__device__ __forceinline__ unsigned long long fma2(unsigned long long a,
                                                   unsigned long long b,
                                                   unsigned long long c) {
    unsigned long long d;
    asm("fma.rn.f32x2 %0, %1, %2, %3;" : "=l"(d) : "l"(a), "l"(b), "l"(c));
    return d;
}
__device__ __forceinline__ float2 unpack2(unsigned long long v) {
    float2 r;
    asm("mov.b64 {%0,%1}, %2;" : "=f"(r.x), "=f"(r.y) : "l"(v));
    return r;
}

// ---------------------------------------------------------------------------
// Main kernel: one thread = TWO samples packed as f32x2. Per-thread buffer
// column in shared ([col*BT + tid], float2 elements -> conflict-free, one
// LDS.64/STS.64 serves both samples). W + indices come from __constant__
// (off the smem/L1tex port). Operand loads prefetched 3 gates ahead; the
// rare reference to gate i-1/i-2 (warp-uniform, compile-time compare) is
// fixed with a predicated reload after the STS. No __syncthreads needed.
// ---------------------------------------------------------------------------
__global__ void __launch_bounds__(BT) circuit_kernel(
    const float* __restrict__ X,
    float* __restrict__ out,
    int n)
{
    extern __shared__ float2 buf[];
    const int tid = threadIdx.x;
    const long long base = (long long)blockIdx.x * SPB;
    const long long rowA = base + tid;
    const long long rowB = base + BT + tid;
    const bool hasA = rowA < n;
    const bool hasB = rowB < n;

    char* bufB = (char*)(buf + tid);            // column stride = COLB bytes

    // ---- stage X rows for both samples (coalesced float4 reads) ----
    const float4* xa = (const float4*)(X + rowA * N_FEAT);
    const float4* xb = (const float4*)(X + rowB * N_FEAT);
    #pragma unroll
    for (int c = 0; c < N_FEAT / 4; c++) {
        float4 va = hasA ? xa[c] : make_float4(0.f, 0.f, 0.f, 0.f);
        float4 vb = hasB ? xb[c] : make_float4(0.f, 0.f, 0.f, 0.f);
        *(float2*)(bufB + (4 * c + 0) * COLB) = make_float2(va.x, vb.x);
        *(float2*)(bufB + (4 * c + 1) * COLB) = make_float2(va.y, vb.y);
        *(float2*)(bufB + (4 * c + 2) * COLB) = make_float2(va.z, vb.z);
        *(float2*)(bufB + (4 * c + 3) * COLB) = make_float2(va.w, vb.w);
    }
    *(float2*)(bufB + 64 * COLB) = make_float2(0.f, 0.f);
    *(float2*)(bufB + 65 * COLB) = make_float2(1.f, 1.f);

    const unsigned long long ONE2  = 0x3f8000003f800000ull;
    const unsigned long long SIGN2 = 0x8000000080000000ull;

    unsigned long long acc[N_OUT];
    #pragma unroll
    for (int j = 0; j < N_OUT; j++) acc[j] = 0ull;

    // ---- software pipeline: idx + operand data 3 gates ahead ----
    int ia[4], ib[4];
    unsigned long long pa[4], pb[4];
    #pragma unroll
    for (int j = 0; j < 4; j++) { int2 t2 = c_idx[j]; ia[j] = t2.x; ib[j] = t2.y; }
    #pragma unroll
    for (int j = 0; j < 3; j++) {
        pa[j] = *(const unsigned long long*)(bufB + ia[j]);
        pb[j] = *(const unsigned long long*)(bufB + ib[j]);
    }

    #pragma unroll
    for (int i = 0; i < N_GATES; i++) {
        const int s = i & 3;
        unsigned long long a = pa[s], b = pb[s];
        const int xs = ia[s], ys = ib[s];

        // patch operands that reference gates i-1 / i-2 (not yet stored at
        // prefetch time): warp-uniform predicate, rare -> predicated reload
        if (i >= 1) {
            const int c1 = (BASE_C + i - 1) * COLB;
            const int c2 = (BASE_C + i - 2) * COLB;   // only valid i>=2
            const bool fa = (xs == c1) | ((i >= 2) & (xs == c2));
            const bool fb = (ys == c1) | ((i >= 2) & (ys == c2));
            if (fa) a = *(const unsigned long long*)(bufB + xs);
            if (fb) b = *(const unsigned long long*)(bufB + ys);
        }

        // g = 1 - a*b (both samples), single packed FMA with negated b
        const unsigned long long g = fma2(a, b ^ SIGN2, ONE2);
        *(unsigned long long*)(bufB + (BASE_C + i) * COLB) = g;

        // acc_j += g * (W[i,j]*scale_j)  -- constant-bank operands
        #pragma unroll
        for (int j = 0; j < N_OUT; j++)
            acc[j] = fma2(g, c_w[i * N_OUT + j], acc[j]);

        // rotate pipeline: idx for gate i+4, operand data for gate i+3
        if (i + 4 < N_GATES) { int2 t2 = c_idx[i + 4]; ia[s] = t2.x; ib[s] = t2.y; }
        if (i + 3 < N_GATES) {
            const int s3 = (i + 3) & 3;
            pa[s3] = *(const unsigned long long*)(bufB + ia[s3]);
            pb[s3] = *(const unsigned long long*)(bufB + ib[s3]);
        }
    }

    // ---- epilogue: unpack (lo = sample A, hi = sample B), store float4 ----
    float2 u[N_OUT];
    #pragma unroll
    for (int j = 0; j < N_OUT; j++) u[j] = unpack2(acc[j]);

    if (hasA) {
        float4* ov = (float4*)(out + rowA * N_OUT);
        ov[0] = make_float4(u[0].x, u[1].x, u[2].x, u[3].x);
        ov[1] = make_float4(u[4].x, u[5].x, u[6].x, u[7].x);
    }
    if (hasB) {
        float4* ov = (float4*)(out + rowB * N_OUT);
        ov[0] = make_float4(u[0].y, u[1].y, u[2].y, u[3].y);
        ov[1] = make_float4(u[4].y, u[5].y, u[6].y, u[7].y);
    }
}

// ---------------------------------------------------------------------------
extern "C" void kernel_launch(void* const* d_in, const int* in_sizes, int n_in,
                              void* d_out, int out_size) {
    const float* X     = (const float*)d_in[0];
    const float* gw    = (const float*)d_in[1];
    const float* W     = (const float*)d_in[2];
    const float* scale = (const float*)d_in[3];
    float* out = (float*)d_out;

    const int n = in_sizes[0] / N_FEAT;

    setup_kernel<<<1, N_GATES * N_OUT>>>(gw, W, scale);

    // copy setup results into constant bank (async D2D, graph-capturable)
    void* p_idx = nullptr;
    void* p_w   = nullptr;
    cudaGetSymbolAddress(&p_idx, d_idx);
    cudaGetSymbolAddress(&p_w,   d_wdup);
    cudaMemcpyToSymbolAsync(c_idx, p_idx, sizeof(int2) * N_GATES, 0,
                            cudaMemcpyDeviceToDevice, 0);
    cudaMemcpyToSymbolAsync(c_w, p_w, sizeof(unsigned long long) * N_GATES * N_OUT, 0,
                            cudaMemcpyDeviceToDevice, 0);

    const size_t smem_bytes = (size_t)MAX_CONN * BT * sizeof(float2);  // 66,560 B
    cudaFuncSetAttribute(circuit_kernel,
                         cudaFuncAttributeMaxDynamicSharedMemorySize,
                         (int)smem_bytes);

    const int grid = (n + SPB - 1) / SPB;
    circuit_kernel<<<grid, BT, smem_bytes>>>(X, out, n);
}

// round 6
// speedup vs baseline: 1.0996x; 1.0633x over previous
#include <cuda_runtime.h>

#define N_FEAT   64
#define N_GATES  64
#define N_OUT    8
#define BASE_C   66                  // N_FEAT + 2
#define MAX_CONN 130
#define BT       128                 // threads per block = samples per block
#define COLB     (BT * 4)            // byte stride between buffer columns

// setup results: pre-scaled byte-offset top2 indices + scale-folded W
__device__ int2  g_idx[N_GATES];                 // {i1*COLB, i2*COLB}
__device__ float g_w[N_GATES * N_OUT];           // W[i][j] * scale[j]

// ---------------------------------------------------------------------------
// Setup: top-2 of masked logits per gate (softmax is monotone -> top-2 of
// logits; strict > scan matches jax.lax.top_k tie-breaking; a*b symmetric so
// only the index set matters). Also fold output_scale into W.
// ---------------------------------------------------------------------------
__global__ void setup_kernel(const float* __restrict__ gw,
                             const float* __restrict__ W,
                             const float* __restrict__ scale) {
    int t = threadIdx.x;
    if (t < N_GATES) {
        int lim = BASE_C + t;
        float v1 = -3.0e38f, v2 = -3.0e38f;
        int i1 = 0, i2 = 0;
        for (int j = 0; j < lim; j++) {
            float v = gw[t * MAX_CONN + j];
            if (v > v1) { v2 = v1; i2 = i1; v1 = v; i1 = j; }
            else if (v > v2) { v2 = v; i2 = j; }
        }
        g_idx[t] = make_int2(i1 * COLB, i2 * COLB);
    }
    if (t < N_GATES * N_OUT)
        g_w[t] = W[t] * scale[t & 7];
}

__device__ __forceinline__ unsigned long long fma2(unsigned long long a,
                                                   unsigned long long b,
                                                   unsigned long long c) {
    unsigned long long d;
    asm("fma.rn.f32x2 %0, %1, %2, %3;" : "=l"(d) : "l"(a), "l"(b), "l"(c));
    return d;
}
__device__ __forceinline__ unsigned long long dup2(float g) {
    unsigned long long r;
    unsigned int u = __float_as_uint(g);
    asm("mov.b64 %0, {%1,%1};" : "=l"(r) : "r"(u));
    return r;
}
__device__ __forceinline__ float2 unpack2(unsigned long long v) {
    float2 r;
    asm("mov.b64 {%0,%1}, %2;" : "=f"(r.x), "=f"(r.y) : "l"(v));
    return r;
}

// ---------------------------------------------------------------------------
// Main kernel: one thread = one sample (scalar buffer column in shared,
// [col*BT + tid] -> warp-uniform column => conflict-free). f32x2 lanes carry
// OUTPUT PAIRS: W rows are read as 2x LDS.128 broadcast and consumed directly
// as packed {w_j, w_j+1} operands -> 4 packed FMAs per gate for 8 outputs,
// no constant-bank loads, no W duplication. Gate operand loads are
// software-pipelined 3 gates ahead; rare references to gates i-1/i-2 are
// fixed by a warp-uniform predicated reload after the STS. No __syncthreads
// after staging (threads touch only their own column slots).
// ---------------------------------------------------------------------------
__global__ void __launch_bounds__(BT) circuit_kernel(
    const float* __restrict__ X,
    float* __restrict__ out,
    int n)
{
    extern __shared__ float smem[];
    float* buf  = smem;                               // MAX_CONN * BT
    float* sw   = smem + MAX_CONN * BT;               // 512 floats (W*scale)
    int2*  sidx = (int2*)(sw + N_GATES * N_OUT);      // 64 int2

    const int tid = threadIdx.x;
    const long long row = (long long)blockIdx.x * BT + tid;
    const bool has = row < n;

    // stage W (512 floats) + indices cooperatively
    #pragma unroll
    for (int k = 0; k < (N_GATES * N_OUT) / BT; k++)
        sw[tid + k * BT] = g_w[tid + k * BT];
    if (tid < N_GATES) sidx[tid] = g_idx[tid];
    __syncthreads();

    char* bufB = (char*)(buf + tid);                  // my column base (bytes)

    // ---- stage my X row (coalesced float4 reads, scalar transposed stores)
    const float4* xv = (const float4*)(X + row * N_FEAT);
    #pragma unroll
    for (int c = 0; c < N_FEAT / 4; c++) {
        float4 v = has ? xv[c] : make_float4(0.f, 0.f, 0.f, 0.f);
        *(float*)(bufB + (4 * c + 0) * COLB) = v.x;
        *(float*)(bufB + (4 * c + 1) * COLB) = v.y;
        *(float*)(bufB + (4 * c + 2) * COLB) = v.z;
        *(float*)(bufB + (4 * c + 3) * COLB) = v.w;
    }
    *(float*)(bufB + 64 * COLB) = 0.0f;
    *(float*)(bufB + 65 * COLB) = 1.0f;

    unsigned long long acc0 = 0ull, acc1 = 0ull, acc2 = 0ull, acc3 = 0ull;

    // ---- software pipeline: indices + operand values 3 gates ahead ----
    int ia[4], ib[4];
    float pa[4], pb[4];
    #pragma unroll
    for (int j = 0; j < 4; j++) { int2 t2 = sidx[j]; ia[j] = t2.x; ib[j] = t2.y; }
    #pragma unroll
    for (int j = 0; j < 3; j++) {
        pa[j] = *(const float*)(bufB + ia[j]);
        pb[j] = *(const float*)(bufB + ib[j]);
    }

    #pragma unroll
    for (int i = 0; i < N_GATES; i++) {
        const int s = i & 3;
        float a = pa[s], b = pb[s];
        const int xs = ia[s], ys = ib[s];

        // patch operands referencing gates i-1/i-2 (stored after prefetch):
        // warp-uniform predicate, rare -> predicated reload
        if (i >= 1) {
            const int c1 = (BASE_C + i - 1) * COLB;
            const int c2 = (BASE_C + i - 2) * COLB;   // used only when i>=2
            const bool fa = (xs == c1) | ((i >= 2) & (xs == c2));
            const bool fb = (ys == c1) | ((i >= 2) & (ys == c2));
            if (fa) a = *(const float*)(bufB + xs);
            if (fb) b = *(const float*)(bufB + ys);
        }

        const float g = 1.0f - a * b;
        *(float*)(bufB + (BASE_C + i) * COLB) = g;

        // 8 outputs as 4 packed FMAs; W pairs straight from smem broadcast
        const unsigned long long gg = dup2(g);
        const ulonglong2* wr = (const ulonglong2*)(sw + i * N_OUT);
        ulonglong2 w01 = wr[0], w23 = wr[1];          // 2x LDS.128 broadcast
        acc0 = fma2(gg, w01.x, acc0);                 // outputs 0,1
        acc1 = fma2(gg, w01.y, acc1);                 // outputs 2,3
        acc2 = fma2(gg, w23.x, acc2);                 // outputs 4,5
        acc3 = fma2(gg, w23.y, acc3);                 // outputs 6,7

        // rotate pipeline: indices for gate i+4, operands for gate i+3
        if (i + 4 < N_GATES) { int2 t2 = sidx[i + 4]; ia[s] = t2.x; ib[s] = t2.y; }
        if (i + 3 < N_GATES) {
            const int s3 = (i + 3) & 3;
            pa[s3] = *(const float*)(bufB + ia[s3]);
            pb[s3] = *(const float*)(bufB + ib[s3]);
        }
    }

    // ---- epilogue: unpack output pairs, store 2x STG.128 (scale prefolded)
    if (has) {
        float2 r01 = unpack2(acc0), r23 = unpack2(acc1);
        float2 r45 = unpack2(acc2), r67 = unpack2(acc3);
        float4* ov = (float4*)(out + row * N_OUT);
        ov[0] = make_float4(r01.x, r01.y, r23.x, r23.y);
        ov[1] = make_float4(r45.x, r45.y, r67.x, r67.y);
    }
}

// ---------------------------------------------------------------------------
extern "C" void kernel_launch(void* const* d_in, const int* in_sizes, int n_in,
                              void* d_out, int out_size) {
    const float* X     = (const float*)d_in[0];
    const float* gw    = (const float*)d_in[1];
    const float* W     = (const float*)d_in[2];
    const float* scale = (const float*)d_in[3];
    float* out = (float*)d_out;

    const int n = in_sizes[0] / N_FEAT;

    setup_kernel<<<1, N_GATES * N_OUT>>>(gw, W, scale);

    const size_t smem_bytes =
        (size_t)MAX_CONN * BT * sizeof(float) +       // 66,560
        (size_t)N_GATES * N_OUT * sizeof(float) +     //  2,048
        (size_t)N_GATES * sizeof(int2);               //    512  => 69,120 B

    cudaFuncSetAttribute(circuit_kernel,
                         cudaFuncAttributeMaxDynamicSharedMemorySize,
                         (int)smem_bytes);

    const int grid = (n + BT - 1) / BT;
    circuit_kernel<<<grid, BT, smem_bytes>>>(X, out, n);
}

// round 8
// speedup vs baseline: 1.3037x; 1.1856x over previous
#include <cuda_runtime.h>

#define N_FEAT   64
#define N_GATES  64
#define N_OUT    8
#define BASE_C   66                   // N_FEAT + 2
#define MAX_CONN 130
#define BT       128                  // threads per block = samples per block
#define COLF     129                  // floats per buffer column (pad: 128+1)
#define COLB     (COLF * 4)           // byte stride between buffer columns
#define BUF_FLOATS (MAX_CONN * COLF + 2)   // +2 pad -> 16B alignment for sw

// setup results
__device__ int2               g_idx[N_GATES];     // {i1*COLB, i2*COLB}
__device__ float              g_w[N_GATES * N_OUT]; // W[i][j]*scale[j]
__device__ unsigned long long g_smask;            // bit i: gate i output is read later

// ---------------------------------------------------------------------------
// Setup: top-2 of masked logits per gate (softmax monotone -> top-2 of
// logits; strict > scan matches jax.lax.top_k; a*b symmetric so only the
// index set matters). Fold output_scale into W. Build dead-store mask.
// ---------------------------------------------------------------------------
__global__ void setup_kernel(const float* __restrict__ gw,
                             const float* __restrict__ W,
                             const float* __restrict__ scale) {
    __shared__ int s1[N_GATES], s2[N_GATES];
    int t = threadIdx.x;
    if (t < N_GATES) {
        int lim = BASE_C + t;
        float v1 = -3.0e38f, v2 = -3.0e38f;
        int i1 = 0, i2 = 0;
        for (int j = 0; j < lim; j++) {
            float v = gw[t * MAX_CONN + j];
            if (v > v1) { v2 = v1; i2 = i1; v1 = v; i1 = j; }
            else if (v > v2) { v2 = v; i2 = j; }
        }
        s1[t] = i1; s2[t] = i2;
        g_idx[t] = make_int2(i1 * COLB, i2 * COLB);
    }
    if (t < N_GATES * N_OUT)
        g_w[t] = W[t] * scale[t & 7];
    __syncthreads();
    if (t == 0) {
        unsigned long long m = 0ull;
        for (int i = 0; i < N_GATES; i++) {
            if (s1[i] >= BASE_C) m |= 1ull << (s1[i] - BASE_C);
            if (s2[i] >= BASE_C) m |= 1ull << (s2[i] - BASE_C);
        }
        g_smask = m;
    }
}

__device__ __forceinline__ unsigned long long fma2(unsigned long long a,
                                                   unsigned long long b,
                                                   unsigned long long c) {
    unsigned long long d;
    asm("fma.rn.f32x2 %0, %1, %2, %3;" : "=l"(d) : "l"(a), "l"(b), "l"(c));
    return d;
}
__device__ __forceinline__ unsigned long long dup2(float g) {
    unsigned long long r;
    unsigned int u = __float_as_uint(g);
    asm("mov.b64 %0, {%1,%1};" : "=l"(r) : "r"(u));
    return r;
}
__device__ __forceinline__ float2 unpack2(unsigned long long v) {
    float2 r;
    asm("mov.b64 {%0,%1}, %2;" : "=f"(r.x), "=f"(r.y) : "l"(v));
    return r;
}

// ---------------------------------------------------------------------------
// Main kernel. Buffer layout: buf[col*COLF + tid] (129-float padded column
// stride -> gate-loop LDS bank = (col+tid)%32, conflict-free).
// X staging: COALESCED float4 loads (warp reads 512B contiguous) + transposed
// scalar STS (2-way bank conflict worst case, one-time) -- replaces the old
// 256B-strided per-row loads that cost 32 wavefronts per LDG.
// Gate loop: f32x2 output-pair accumulation (W pairs via LDS.128 broadcast),
// operand loads prefetched 3 gates ahead, rare refs to gates i-1/i-2 patched
// by warp-uniform predicated reload, dead g-stores skipped via mask.
// ---------------------------------------------------------------------------
__global__ void __launch_bounds__(BT) circuit_kernel(
    const float* __restrict__ X,
    float* __restrict__ out,
    int n)
{
    extern __shared__ float smem[];
    float* buf  = smem;                               // BUF_FLOATS
    float* sw   = smem + BUF_FLOATS;                  // 512 floats, 16B aligned
    int2*  sidx = (int2*)(sw + N_GATES * N_OUT);      // 64 int2

    const int tid = threadIdx.x;
    const long long row = (long long)blockIdx.x * BT + tid;
    const bool has = row < n;

    // stage W + indices cooperatively
    #pragma unroll
    for (int k = 0; k < (N_GATES * N_OUT) / BT; k++)
        sw[tid + k * BT] = g_w[tid + k * BT];
    if (tid < N_GATES) sidx[tid] = g_idx[tid];

    // ---- coalesced X staging with transpose ----
    // block tile = BT rows x 64 feats = 8192 floats; thread t handles float4
    // #(t + 128*kk): col0 = 4*(t%16) (fixed), row = t/16 + 8*kk.
    {
        const float4* xb = (const float4*)(X + (long long)blockIdx.x * (BT * N_FEAT));
        const long long lim4 = ((long long)n * N_FEAT) >> 2;   // #float4 in X
        const long long b4   = (long long)blockIdx.x * (BT * N_FEAT / 4);
        const int col0 = 4 * (tid & 15);
        const int row0 = tid >> 4;
        #pragma unroll
        for (int kk = 0; kk < 16; kk++) {
            const int i4 = tid + BT * kk;
            float4 v = (b4 + i4 < lim4) ? xb[i4] : make_float4(0.f, 0.f, 0.f, 0.f);
            float* dst = buf + row0 + 8 * kk;
            dst[(col0 + 0) * COLF] = v.x;
            dst[(col0 + 1) * COLF] = v.y;
            dst[(col0 + 2) * COLF] = v.z;
            dst[(col0 + 3) * COLF] = v.w;
        }
    }
    buf[64 * COLF + tid] = 0.0f;
    buf[65 * COLF + tid] = 1.0f;
    __syncthreads();

    const unsigned long long smask = g_smask;         // L2-broadcast LDG
    char* bufB = (char*)buf + tid * 4;                // my row base (bytes)

    unsigned long long acc0 = 0ull, acc1 = 0ull, acc2 = 0ull, acc3 = 0ull;

    // ---- software pipeline: indices + operand values 3 gates ahead ----
    int ia[4], ib[4];
    float pa[4], pb[4];
    #pragma unroll
    for (int j = 0; j < 4; j++) { int2 t2 = sidx[j]; ia[j] = t2.x; ib[j] = t2.y; }
    #pragma unroll
    for (int j = 0; j < 3; j++) {
        pa[j] = *(const float*)(bufB + ia[j]);
        pb[j] = *(const float*)(bufB + ib[j]);
    }

    #pragma unroll
    for (int i = 0; i < N_GATES; i++) {
        const int s = i & 3;
        float a = pa[s], b = pb[s];
        const int xs = ia[s], ys = ib[s];

        // patch operands referencing gates i-1/i-2 (stored after prefetch):
        // warp-uniform predicate, rare -> predicated reload. Any gate that is
        // referenced has its store bit set, so the reload always sees data.
        if (i >= 1) {
            const int c1 = (BASE_C + i - 1) * COLB;
            const int c2 = (BASE_C + i - 2) * COLB;   // used only when i>=2
            const bool fa = (xs == c1) | ((i >= 2) & (xs == c2));
            const bool fb = (ys == c1) | ((i >= 2) & (ys == c2));
            if (fa) a = *(const float*)(bufB + xs);
            if (fb) b = *(const float*)(bufB + ys);
        }

        const float g = 1.0f - a * b;
        if (smask & (1ull << i))                      // skip dead stores
            *(float*)(bufB + (BASE_C + i) * COLB) = g;

        // 8 outputs as 4 packed FMAs; W pairs via LDS.128 broadcast
        const unsigned long long gg = dup2(g);
        const ulonglong2* wr = (const ulonglong2*)(sw + i * N_OUT);
        ulonglong2 w01 = wr[0], w23 = wr[1];
        acc0 = fma2(gg, w01.x, acc0);
        acc1 = fma2(gg, w01.y, acc1);
        acc2 = fma2(gg, w23.x, acc2);
        acc3 = fma2(gg, w23.y, acc3);

        // rotate pipeline: indices for gate i+4, operands for gate i+3
        if (i + 4 < N_GATES) { int2 t2 = sidx[i + 4]; ia[s] = t2.x; ib[s] = t2.y; }
        if (i + 3 < N_GATES) {
            const int s3 = (i + 3) & 3;
            pa[s3] = *(const float*)(bufB + ia[s3]);
            pb[s3] = *(const float*)(bufB + ib[s3]);
        }
    }

    // ---- epilogue: scale already folded into W ----
    if (has) {
        float2 r01 = unpack2(acc0), r23 = unpack2(acc1);
        float2 r45 = unpack2(acc2), r67 = unpack2(acc3);
        float4* ov = (float4*)(out + row * N_OUT);
        ov[0] = make_float4(r01.x, r01.y, r23.x, r23.y);
        ov[1] = make_float4(r45.x, r45.y, r67.x, r67.y);
    }
}

// ---------------------------------------------------------------------------
extern "C" void kernel_launch(void* const* d_in, const int* in_sizes, int n_in,
                              void* d_out, int out_size) {
    const float* X     = (const float*)d_in[0];
    const float* gw    = (const float*)d_in[1];
    const float* W     = (const float*)d_in[2];
    const float* scale = (const float*)d_in[3];
    float* out = (float*)d_out;

    const int n = in_sizes[0] / N_FEAT;

    setup_kernel<<<1, N_GATES * N_OUT>>>(gw, W, scale);

    const size_t smem_bytes =
        (size_t)BUF_FLOATS * sizeof(float) +          // 67,088
        (size_t)N_GATES * N_OUT * sizeof(float) +     //  2,048
        (size_t)N_GATES * sizeof(int2);               //    512 => 69,648 B

    cudaFuncSetAttribute(circuit_kernel,
                         cudaFuncAttributeMaxDynamicSharedMemorySize,
                         (int)smem_bytes);

    const int grid = (n + BT - 1) / BT;
    circuit_kernel<<<grid, BT, smem_bytes>>>(X, out, n);
}

// round 9
// speedup vs baseline: 1.3308x; 1.0208x over previous
#include <cuda_runtime.h>

#define N_FEAT   64
#define N_GATES  64
#define N_OUT    8
#define BASE_C   66                   // N_FEAT + 2
#define MAX_CONN 130
#define BT       128                  // threads per block = samples per tile
#define COLF     129                  // floats per buffer column (pad 128+1)
#define COLB     (COLF * 4)           // byte stride between buffer columns
#define BUF_FLOATS (MAX_CONN * COLF + 2)
#define NBLOCKS  444                  // 148 SMs x 3 resident blocks

// setup results
__device__ int2               g_idx[N_GATES];       // {i1*COLB, i2*COLB}
__device__ float              g_w[N_GATES * N_OUT]; // W[i][j]*scale[j]
__device__ unsigned long long g_smask;              // bit i: gate i output read later

// ---------------------------------------------------------------------------
// Setup: top-2 of masked logits per gate (softmax monotone -> top-2 of
// logits; strict > scan matches jax.lax.top_k; a*b symmetric so only the
// index set matters). Fold output_scale into W. Build dead-store mask.
// ---------------------------------------------------------------------------
__global__ void setup_kernel(const float* __restrict__ gw,
                             const float* __restrict__ W,
                             const float* __restrict__ scale) {
    __shared__ int s1[N_GATES], s2[N_GATES];
    int t = threadIdx.x;
    if (t < N_GATES) {
        int lim = BASE_C + t;
        float v1 = -3.0e38f, v2 = -3.0e38f;
        int i1 = 0, i2 = 0;
        for (int j = 0; j < lim; j++) {
            float v = gw[t * MAX_CONN + j];
            if (v > v1) { v2 = v1; i2 = i1; v1 = v; i1 = j; }
            else if (v > v2) { v2 = v; i2 = j; }
        }
        s1[t] = i1; s2[t] = i2;
        g_idx[t] = make_int2(i1 * COLB, i2 * COLB);
    }
    if (t < N_GATES * N_OUT)
        g_w[t] = W[t] * scale[t & 7];
    __syncthreads();
    if (t == 0) {
        unsigned long long m = 0ull;
        for (int i = 0; i < N_GATES; i++) {
            if (s1[i] >= BASE_C) m |= 1ull << (s1[i] - BASE_C);
            if (s2[i] >= BASE_C) m |= 1ull << (s2[i] - BASE_C);
        }
        g_smask = m;
    }
}

__device__ __forceinline__ unsigned long long fma2(unsigned long long a,
                                                   unsigned long long b,
                                                   unsigned long long c) {
    unsigned long long d;
    asm("fma.rn.f32x2 %0, %1, %2, %3;" : "=l"(d) : "l"(a), "l"(b), "l"(c));
    return d;
}
__device__ __forceinline__ unsigned long long dup2(float g) {
    unsigned long long r;
    unsigned int u = __float_as_uint(g);
    asm("mov.b64 %0, {%1,%1};" : "=l"(r) : "r"(u));
    return r;
}
__device__ __forceinline__ float2 unpack2(unsigned long long v) {
    float2 r;
    asm("mov.b64 {%0,%1}, %2;" : "=f"(r.x), "=f"(r.y) : "l"(v));
    return r;
}

// ---------------------------------------------------------------------------
// Persistent main kernel. Each block grid-strides over sample tiles; the 16
// coalesced float4 LDGs for tile t+1 are issued BEFORE the gate loop of tile
// t, so DRAM streams continuously instead of bursting between compute phases
// (previous profiles showed HBM at 27% duty pacing the waves).
// Buffer: buf[col*COLF + tid], 129-float stride -> conflict-free gate-loop
// LDS; staging transpose worst-case 2-way. Gate loop identical to R7:
// f32x2 output-pair accumulation, distance-3 operand prefetch, warp-uniform
// patch reloads, dead-store mask.
// ---------------------------------------------------------------------------
__global__ void __launch_bounds__(BT, 3) circuit_kernel(
    const float* __restrict__ X,
    float* __restrict__ out,
    int n)
{
    extern __shared__ float smem[];
    float* buf  = smem;                               // BUF_FLOATS
    float* sw   = smem + BUF_FLOATS;                  // 512 floats, 16B aligned
    int2*  sidx = (int2*)(sw + N_GATES * N_OUT);      // 64 int2

    const int tid = threadIdx.x;
    const int nt  = (n + BT - 1) / BT;                // number of tiles

    // one-time staging: W, indices, constant columns
    #pragma unroll
    for (int k = 0; k < (N_GATES * N_OUT) / BT; k++)
        sw[tid + k * BT] = g_w[tid + k * BT];
    if (tid < N_GATES) sidx[tid] = g_idx[tid];
    buf[64 * COLF + tid] = 0.0f;
    buf[65 * COLF + tid] = 1.0f;

    const unsigned long long smask = g_smask;
    char* bufB = (char*)buf + tid * 4;                // my row base (bytes)

    const float4* xb4 = (const float4*)X;
    const long long lim4 = ((long long)n * N_FEAT) >> 2;
    const int col0 = 4 * (tid & 15);
    const int row0 = tid >> 4;

    // prefetch X for my first tile
    float4 xr[16];
    {
        const long long b4 = (long long)blockIdx.x * (BT * N_FEAT / 4);
        #pragma unroll
        for (int kk = 0; kk < 16; kk++) {
            const long long i4 = b4 + tid + BT * kk;
            xr[kk] = (i4 < lim4) ? xb4[i4] : make_float4(0.f, 0.f, 0.f, 0.f);
        }
    }
    __syncthreads();

    for (int tile = blockIdx.x; tile < nt; tile += NBLOCKS) {
        // ---- transpose staged registers into the column-major buffer ----
        #pragma unroll
        for (int kk = 0; kk < 16; kk++) {
            float* dst = buf + row0 + 8 * kk;
            dst[(col0 + 0) * COLF] = xr[kk].x;
            dst[(col0 + 1) * COLF] = xr[kk].y;
            dst[(col0 + 2) * COLF] = xr[kk].z;
            dst[(col0 + 3) * COLF] = xr[kk].w;
        }
        __syncthreads();

        // ---- issue LDGs for the NEXT tile; land during the gate loop ----
        const int ntile = tile + NBLOCKS;
        if (ntile < nt) {
            const long long b4 = (long long)ntile * (BT * N_FEAT / 4);
            #pragma unroll
            for (int kk = 0; kk < 16; kk++) {
                const long long i4 = b4 + tid + BT * kk;
                xr[kk] = (i4 < lim4) ? xb4[i4] : make_float4(0.f, 0.f, 0.f, 0.f);
            }
        }

        // ---- gate loop (identical to proven R7 loop) ----
        unsigned long long acc0 = 0ull, acc1 = 0ull, acc2 = 0ull, acc3 = 0ull;

        int ia[4], ib[4];
        float pa[4], pb[4];
        #pragma unroll
        for (int j = 0; j < 4; j++) { int2 t2 = sidx[j]; ia[j] = t2.x; ib[j] = t2.y; }
        #pragma unroll
        for (int j = 0; j < 3; j++) {
            pa[j] = *(const float*)(bufB + ia[j]);
            pb[j] = *(const float*)(bufB + ib[j]);
        }

        #pragma unroll
        for (int i = 0; i < N_GATES; i++) {
            const int s = i & 3;
            float a = pa[s], b = pb[s];
            const int xs = ia[s], ys = ib[s];

            if (i >= 1) {
                const int c1 = (BASE_C + i - 1) * COLB;
                const int c2 = (BASE_C + i - 2) * COLB;
                const bool fa = (xs == c1) | ((i >= 2) & (xs == c2));
                const bool fb = (ys == c1) | ((i >= 2) & (ys == c2));
                if (fa) a = *(const float*)(bufB + xs);
                if (fb) b = *(const float*)(bufB + ys);
            }

            const float g = 1.0f - a * b;
            if (smask & (1ull << i))
                *(float*)(bufB + (BASE_C + i) * COLB) = g;

            const unsigned long long gg = dup2(g);
            const ulonglong2* wr = (const ulonglong2*)(sw + i * N_OUT);
            ulonglong2 w01 = wr[0], w23 = wr[1];
            acc0 = fma2(gg, w01.x, acc0);
            acc1 = fma2(gg, w01.y, acc1);
            acc2 = fma2(gg, w23.x, acc2);
            acc3 = fma2(gg, w23.y, acc3);

            if (i + 4 < N_GATES) { int2 t2 = sidx[i + 4]; ia[s] = t2.x; ib[s] = t2.y; }
            if (i + 3 < N_GATES) {
                const int s3 = (i + 3) & 3;
                pa[s3] = *(const float*)(bufB + ia[s3]);
                pb[s3] = *(const float*)(bufB + ib[s3]);
            }
        }

        // ---- epilogue (scale prefolded into W) ----
        const long long row = (long long)tile * BT + tid;
        if (row < n) {
            float2 r01 = unpack2(acc0), r23 = unpack2(acc1);
            float2 r45 = unpack2(acc2), r67 = unpack2(acc3);
            float4* ov = (float4*)(out + row * N_OUT);
            ov[0] = make_float4(r01.x, r01.y, r23.x, r23.y);
            ov[1] = make_float4(r45.x, r45.y, r67.x, r67.y);
        }

        __syncthreads();   // buffer reads done before next tile's transpose
    }
}

// ---------------------------------------------------------------------------
extern "C" void kernel_launch(void* const* d_in, const int* in_sizes, int n_in,
                              void* d_out, int out_size) {
    const float* X     = (const float*)d_in[0];
    const float* gw    = (const float*)d_in[1];
    const float* W     = (const float*)d_in[2];
    const float* scale = (const float*)d_in[3];
    float* out = (float*)d_out;

    const int n = in_sizes[0] / N_FEAT;

    setup_kernel<<<1, N_GATES * N_OUT>>>(gw, W, scale);

    const size_t smem_bytes =
        (size_t)BUF_FLOATS * sizeof(float) +          // 67,088
        (size_t)N_GATES * N_OUT * sizeof(float) +     //  2,048
        (size_t)N_GATES * sizeof(int2);               //    512 => 69,648 B

    cudaFuncSetAttribute(circuit_kernel,
                         cudaFuncAttributeMaxDynamicSharedMemorySize,
                         (int)smem_bytes);

    const int nt = (n + BT - 1) / BT;
    const int grid = (nt < NBLOCKS) ? nt : NBLOCKS;
    circuit_kernel<<<grid, BT, smem_bytes>>>(X, out, n);
}